// round 16
// baseline (speedup 1.0000x reference)
#include <cuda_runtime.h>
#include <cuda_bf16.h>
#include <math.h>

#define TT 4096
#define EE 768
#define HH 12
#define DD 64
#define WIN 512
#define OUT_ELEMS (TT*EE)                 // 3145728
#define ATTN_ELEMS ((size_t)HH*TT*TT)     // 201326592

typedef unsigned long long ull;
typedef unsigned int u32;

// cp.async helpers (16B)
#define CPA16(dst, src) asm volatile("cp.async.cg.shared.global [%0], [%1], 16;" :: "r"(dst), "l"(src))
#define CPC()  asm volatile("cp.async.commit_group;")
#define CPW0() asm volatile("cp.async.wait_group 0;" ::: "memory")
#define CPW1() asm volatile("cp.async.wait_group 1;" ::: "memory")

// ---------------- scratch (device globals: allocation-free) ----------------
__device__ __align__(16) float g_d[HH*TT];

// bf16 two-term split buffers
__device__ __align__(16) __nv_bfloat16 g_xh[TT*EE], g_xl[TT*EE];
__device__ __align__(16) __nv_bfloat16 g_Wh[4][EE*EE], g_Wl[4][EE*EE];
__device__ __align__(16) __nv_bfloat16 g_Qh[TT*EE], g_Ql[TT*EE];
__device__ __align__(16) __nv_bfloat16 g_Kh[TT*EE], g_Kl[TT*EE];
__device__ __align__(16) __nv_bfloat16 g_Vh[TT*EE], g_Vl[TT*EE];
__device__ __align__(16) __nv_bfloat16 g_ch[TT*EE], g_cl[TT*EE];   // ctx hi/lo

// ---------------- helpers ----------------------------------------------------
__device__ __forceinline__ u32 pack_bf16x2(float a, float b) {
    __nv_bfloat16 ha = __float2bfloat16_rn(a), hb = __float2bfloat16_rn(b);
    return ((u32)__bfloat16_as_ushort(hb) << 16) | __bfloat16_as_ushort(ha);
}
// fast exp on FMA pipe: exp(x) = 2^(x*log2e), poly deg-5, ~2e-7 rel err
__device__ __forceinline__ float fast_exp(float x) {
    float y = fmaxf(x * 1.4426950408889634f, -126.0f);
    float n = floorf(y);
    float f = y - n;
    float p = 1.8775767e-3f;
    p = fmaf(p, f, 8.9893397e-3f);
    p = fmaf(p, f, 5.5826318e-2f);
    p = fmaf(p, f, 2.4015361e-1f);
    p = fmaf(p, f, 6.9315308e-1f);
    p = fmaf(p, f, 1.0f);
    float s = __int_as_float(((int)n + 127) << 23);
    return p * s;
}

// ---------------- fp32 -> bf16 hi/lo split (single fused launch) ------------
#define XN4 (OUT_ELEMS/4)          // 786432
#define WN4 (EE*EE/4)              // 147456
#define CVT_TOTAL (XN4 + 4*WN4)    // 1376256
__global__ __launch_bounds__(256) void cvt_kernel(
    const float* __restrict__ x,  const float* __restrict__ Wq,
    const float* __restrict__ Wk, const float* __restrict__ Wv,
    const float* __restrict__ Wo)
{
    int i = blockIdx.x * 256 + threadIdx.x;
    if (i >= CVT_TOTAL) return;
    const float* src; __nv_bfloat16 *hi, *lo; int idx;
    if (i < XN4) { src = x; hi = g_xh; lo = g_xl; idx = i; }
    else {
        int j = i - XN4;
        int w = j / WN4;
        idx = j - w * WN4;
        src = (w == 0) ? Wq : (w == 1) ? Wk : (w == 2) ? Wv : Wo;
        hi = g_Wh[w]; lo = g_Wl[w];
    }
    float4 v = ((const float4*)src)[idx];
    float h0f = __bfloat162float(__float2bfloat16_rn(v.x));
    float h1f = __bfloat162float(__float2bfloat16_rn(v.y));
    float h2f = __bfloat162float(__float2bfloat16_rn(v.z));
    float h3f = __bfloat162float(__float2bfloat16_rn(v.w));
    uint2 hp, lp;
    hp.x = pack_bf16x2(v.x, v.y);
    hp.y = pack_bf16x2(v.z, v.w);
    lp.x = pack_bf16x2(v.x - h0f, v.y - h1f);
    lp.y = pack_bf16x2(v.z - h2f, v.w - h3f);
    ((uint2*)hi)[idx] = hp;
    ((uint2*)lo)[idx] = lp;
}

// ---------------- mma helpers ------------------------------------------------
__device__ __forceinline__ u32 smem_u32(const void* p) {
    return (u32)__cvta_generic_to_shared(p);
}
__device__ __forceinline__ void ldsm_x4(u32 addr, u32& r0, u32& r1, u32& r2, u32& r3) {
    asm volatile("ldmatrix.sync.aligned.m8n8.x4.shared.b16 {%0,%1,%2,%3}, [%4];"
        : "=r"(r0), "=r"(r1), "=r"(r2), "=r"(r3) : "r"(addr));
}
__device__ __forceinline__ void ldsm_x4t(u32 addr, u32& r0, u32& r1, u32& r2, u32& r3) {
    asm volatile("ldmatrix.sync.aligned.m8n8.x4.trans.shared.b16 {%0,%1,%2,%3}, [%4];"
        : "=r"(r0), "=r"(r1), "=r"(r2), "=r"(r3) : "r"(addr));
}
__device__ __forceinline__ void mma_bf16(float* d, const u32* a, u32 b0, u32 b1) {
    asm volatile(
        "mma.sync.aligned.m16n8k16.row.col.f32.bf16.bf16.f32 "
        "{%0,%1,%2,%3}, {%4,%5,%6,%7}, {%8,%9}, {%0,%1,%2,%3};"
        : "+f"(d[0]), "+f"(d[1]), "+f"(d[2]), "+f"(d[3])
        : "r"(a[0]), "r"(a[1]), "r"(a[2]), "r"(a[3]), "r"(b0), "r"(b1));
}

// ---------------- split-bf16 GEMM, cp.async double-buffered -----------------
#define LDA 40
#define LDB 72
#define A_BUF (128*LDA)
#define B_BUF (32*LDB)
#define GEMM_SMEM ((2*A_BUF*2 + 2*B_BUF*2) * 2)   // 59392 bytes
#define NKI 24
__global__ __launch_bounds__(256) void bgemm_kernel(float* __restrict__ Cext, int wsel)
{
    if (wsel < 0) wsel = blockIdx.z;
    const __nv_bfloat16 *Ah, *Al;
    const __nv_bfloat16 *Bh = g_Wh[wsel], *Bl = g_Wl[wsel];
    __nv_bfloat16 *Ch = nullptr, *Cl = nullptr;
    if (wsel < 3) {
        Ah = g_xh; Al = g_xl;
        Ch = (wsel == 0) ? g_Qh : (wsel == 1) ? g_Kh : g_Vh;
        Cl = (wsel == 0) ? g_Ql : (wsel == 1) ? g_Kl : g_Vl;
    } else {
        Ah = g_ch; Al = g_cl;
    }

    extern __shared__ __nv_bfloat16 smb[];
    __nv_bfloat16* bAh = smb;
    __nv_bfloat16* bAl = bAh + 2 * A_BUF;
    __nv_bfloat16* bBh = bAl + 2 * A_BUF;
    __nv_bfloat16* bBl = bBh + 2 * B_BUF;

    int tid = threadIdx.x;
    int wid = tid >> 5, lane = tid & 31;
    int m0 = blockIdx.y * 128, n0 = blockIdx.x * 64;
    int wm0 = (wid >> 1) * 32, wn0 = (wid & 1) * 32;
    int lr = lane & 15, lc = lane >> 4;

    int ar0 = tid >> 2,            akc = (tid & 3) * 8;
    int ar1 = (tid + 256) >> 2,    akc1 = ((tid + 256) & 3) * 8;
    int brow = tid >> 3,           bnc = (tid & 7) * 8;

    float acc[2][4][4];
    #pragma unroll
    for (int mi = 0; mi < 2; mi++)
        #pragma unroll
        for (int nj = 0; nj < 4; nj++)
            #pragma unroll
            for (int q = 0; q < 4; q++) acc[mi][nj][q] = 0.f;

    {
        int k0 = 0;
        CPA16(smem_u32(bAh + ar0 * LDA + akc),  Ah + (size_t)(m0 + ar0) * 768 + k0 + akc);
        CPA16(smem_u32(bAh + ar1 * LDA + akc1), Ah + (size_t)(m0 + ar1) * 768 + k0 + akc1);
        CPA16(smem_u32(bAl + ar0 * LDA + akc),  Al + (size_t)(m0 + ar0) * 768 + k0 + akc);
        CPA16(smem_u32(bAl + ar1 * LDA + akc1), Al + (size_t)(m0 + ar1) * 768 + k0 + akc1);
        CPA16(smem_u32(bBh + brow * LDB + bnc), Bh + (size_t)(k0 + brow) * 768 + n0 + bnc);
        CPA16(smem_u32(bBl + brow * LDB + bnc), Bl + (size_t)(k0 + brow) * 768 + n0 + bnc);
        CPC();
    }

    int buf = 0;
    for (int ki = 0; ki < NKI; ki++) {
        CPW0();
        __syncthreads();
        if (ki + 1 < NKI) {
            int k0 = (ki + 1) * 32;
            int ob = (buf ^ 1);
            __nv_bfloat16* dAh = bAh + ob * A_BUF;
            __nv_bfloat16* dAl = bAl + ob * A_BUF;
            __nv_bfloat16* dBh = bBh + ob * B_BUF;
            __nv_bfloat16* dBl = bBl + ob * B_BUF;
            CPA16(smem_u32(dAh + ar0 * LDA + akc),  Ah + (size_t)(m0 + ar0) * 768 + k0 + akc);
            CPA16(smem_u32(dAh + ar1 * LDA + akc1), Ah + (size_t)(m0 + ar1) * 768 + k0 + akc1);
            CPA16(smem_u32(dAl + ar0 * LDA + akc),  Al + (size_t)(m0 + ar0) * 768 + k0 + akc);
            CPA16(smem_u32(dAl + ar1 * LDA + akc1), Al + (size_t)(m0 + ar1) * 768 + k0 + akc1);
            CPA16(smem_u32(dBh + brow * LDB + bnc), Bh + (size_t)(k0 + brow) * 768 + n0 + bnc);
            CPA16(smem_u32(dBl + brow * LDB + bnc), Bl + (size_t)(k0 + brow) * 768 + n0 + bnc);
            CPC();
        }

        const __nv_bfloat16* cAh = bAh + buf * A_BUF;
        const __nv_bfloat16* cAl = bAl + buf * A_BUF;
        const __nv_bfloat16* cBh = bBh + buf * B_BUF;
        const __nv_bfloat16* cBl = bBl + buf * B_BUF;

        #pragma unroll
        for (int kk = 0; kk < 32; kk += 16) {
            u32 ah[2][4], al[2][4], bh[2][4], bl[2][4];
            #pragma unroll
            for (int mi = 0; mi < 2; mi++) {
                u32 adr = smem_u32(cAh + (wm0 + mi * 16 + lr) * LDA + kk + lc * 8);
                ldsm_x4(adr, ah[mi][0], ah[mi][1], ah[mi][2], ah[mi][3]);
                adr = smem_u32(cAl + (wm0 + mi * 16 + lr) * LDA + kk + lc * 8);
                ldsm_x4(adr, al[mi][0], al[mi][1], al[mi][2], al[mi][3]);
            }
            #pragma unroll
            for (int nj2 = 0; nj2 < 2; nj2++) {
                u32 adr = smem_u32(cBh + (kk + lr) * LDB + wn0 + nj2 * 16 + lc * 8);
                ldsm_x4t(adr, bh[nj2][0], bh[nj2][1], bh[nj2][2], bh[nj2][3]);
                adr = smem_u32(cBl + (kk + lr) * LDB + wn0 + nj2 * 16 + lc * 8);
                ldsm_x4t(adr, bl[nj2][0], bl[nj2][1], bl[nj2][2], bl[nj2][3]);
            }
            #pragma unroll
            for (int mi = 0; mi < 2; mi++)
                #pragma unroll
                for (int nj = 0; nj < 4; nj++) {
                    int j2 = nj >> 1, hf = (nj & 1) * 2;
                    mma_bf16(acc[mi][nj], ah[mi], bh[j2][hf], bh[j2][hf + 1]);
                    mma_bf16(acc[mi][nj], ah[mi], bl[j2][hf], bl[j2][hf + 1]);
                    mma_bf16(acc[mi][nj], al[mi], bh[j2][hf], bh[j2][hf + 1]);
                }
        }
        buf ^= 1;
        __syncthreads();
    }

    int g = lane >> 2, t4 = lane & 3;
    #pragma unroll
    for (int mi = 0; mi < 2; mi++)
        #pragma unroll
        for (int nj = 0; nj < 4; nj++) {
            int row = m0 + wm0 + mi * 16 + g;
            int col = n0 + wn0 + nj * 8 + t4 * 2;
            if (wsel == 3) {
                *(float2*)&Cext[(size_t)row * 768 + col] =
                    make_float2(acc[mi][nj][0], acc[mi][nj][1]);
                *(float2*)&Cext[(size_t)(row + 8) * 768 + col] =
                    make_float2(acc[mi][nj][2], acc[mi][nj][3]);
            } else {
                #pragma unroll
                for (int rr = 0; rr < 2; rr++) {
                    float v0 = acc[mi][nj][rr * 2], v1 = acc[mi][nj][rr * 2 + 1];
                    float h0 = __bfloat162float(__float2bfloat16_rn(v0));
                    float h1 = __bfloat162float(__float2bfloat16_rn(v1));
                    size_t off = (size_t)(row + rr * 8) * 768 + col;
                    *(u32*)(Ch + off) = pack_bf16x2(v0, v1);
                    *(u32*)(Cl + off) = pack_bf16x2(v0 - h0, v1 - h1);
                }
            }
        }
}

// ---------------- d bias -----------------------------------------------------
__global__ __launch_bounds__(1024) void dbias_kernel(const float* __restrict__ u)
{
    int h = blockIdx.x, tid = threadIdx.x;
    __shared__ float su[64];
    __shared__ float red[32];
    if (tid < 64) su[tid] = u[h * 64 + tid];
    __syncthreads();

    float vals[4];
    float lsum = 0.f;
    #pragma unroll
    for (int j = 0; j < 4; j++) {
        int t = j * 1024 + tid;
        const __nv_bfloat162* kh = (const __nv_bfloat162*)(g_Kh + (size_t)t * 768 + h * 64);
        const __nv_bfloat162* kl = (const __nv_bfloat162*)(g_Kl + (size_t)t * 768 + h * 64);
        float dot = 0.f;
        #pragma unroll
        for (int q = 0; q < 32; q++) {
            float2 hv = __bfloat1622float2(kh[q]);
            float2 lv = __bfloat1622float2(kl[q]);
            dot += (hv.x + lv.x) * su[q * 2] + (hv.y + lv.y) * su[q * 2 + 1];
        }
        vals[j] = dot;
        lsum += dot;
    }
    #pragma unroll
    for (int o = 16; o > 0; o >>= 1) lsum += __shfl_xor_sync(0xffffffffu, lsum, o);
    if ((tid & 31) == 0) red[tid >> 5] = lsum;
    __syncthreads();
    if (tid < 32) {
        float v = red[tid];
        #pragma unroll
        for (int o = 16; o > 0; o >>= 1) v += __shfl_xor_sync(0xffffffffu, v, o);
        if (tid == 0) red[0] = v * (1.0f / 4096.0f);
    }
    __syncthreads();
    float mean = red[0];
    #pragma unroll
    for (int j = 0; j < 4; j++)
        g_d[h * 4096 + j * 1024 + tid] = vals[j] - mean;
}

// ---------------- attention: recompute-softmax, no sL band buffer -----------
// smem: 10 bf16 tiles [64][72] (Q,K query hi/lo; Kb,Qb key hi/lo (reused as
// Ph,Pl); V hi/lo) + sd + (m,s) reduction scratch = 95.5 KB -> 2 CTAs/SM.
#define TLD 72
#define TILE_B (64*TLD)           // bf16 elements per tile
#define ATT_SMEM (10*TILE_B*2 + 576*4 + 256*4)

struct LogitsFrag { float a1[4][4]; float a2[4][4]; };

__device__ __forceinline__ void logits_mma(
    const __nv_bfloat16 (*sQh)[TLD], const __nv_bfloat16 (*sQl)[TLD],
    const __nv_bfloat16 (*sKqh)[TLD], const __nv_bfloat16 (*sKql)[TLD],
    const __nv_bfloat16 (*sKbh)[TLD], const __nv_bfloat16 (*sKbl)[TLD],
    const __nv_bfloat16 (*sQbh)[TLD], const __nv_bfloat16 (*sQbl)[TLD],
    int wm0, int wn0, int lr, int lc, LogitsFrag& F)
{
    #pragma unroll
    for (int nj = 0; nj < 4; nj++)
        #pragma unroll
        for (int q = 0; q < 4; q++) { F.a1[nj][q] = 0.f; F.a2[nj][q] = 0.f; }

    #pragma unroll
    for (int kk = 0; kk < 64; kk += 16) {
        u32 aqh[4], aql[4], akh[4], akl[4];
        u32 adr = smem_u32(&sQh[wm0 + lr][kk + lc * 8]);
        ldsm_x4(adr, aqh[0], aqh[1], aqh[2], aqh[3]);
        adr = smem_u32(&sQl[wm0 + lr][kk + lc * 8]);
        ldsm_x4(adr, aql[0], aql[1], aql[2], aql[3]);
        adr = smem_u32(&sKqh[wm0 + lr][kk + lc * 8]);
        ldsm_x4(adr, akh[0], akh[1], akh[2], akh[3]);
        adr = smem_u32(&sKql[wm0 + lr][kk + lc * 8]);
        ldsm_x4(adr, akl[0], akl[1], akl[2], akl[3]);

        u32 bkh[2][4], bkl[2][4], bqh[2][4], bql[2][4];
        #pragma unroll
        for (int nj2 = 0; nj2 < 2; nj2++) {
            adr = smem_u32(&sKbh[wn0 + nj2 * 16 + lr][kk + lc * 8]);
            ldsm_x4(adr, bkh[nj2][0], bkh[nj2][1], bkh[nj2][2], bkh[nj2][3]);
            adr = smem_u32(&sKbl[wn0 + nj2 * 16 + lr][kk + lc * 8]);
            ldsm_x4(adr, bkl[nj2][0], bkl[nj2][1], bkl[nj2][2], bkl[nj2][3]);
            adr = smem_u32(&sQbh[wn0 + nj2 * 16 + lr][kk + lc * 8]);
            ldsm_x4(adr, bqh[nj2][0], bqh[nj2][1], bqh[nj2][2], bqh[nj2][3]);
            adr = smem_u32(&sQbl[wn0 + nj2 * 16 + lr][kk + lc * 8]);
            ldsm_x4(adr, bql[nj2][0], bql[nj2][1], bql[nj2][2], bql[nj2][3]);
        }
        #pragma unroll
        for (int nj = 0; nj < 4; nj++) {
            int j2 = nj >> 1, nh = nj & 1;
            mma_bf16(F.a1[nj], aqh, bkh[j2][nh], bkh[j2][nh + 2]);
            mma_bf16(F.a1[nj], aqh, bkl[j2][nh], bkl[j2][nh + 2]);
            mma_bf16(F.a1[nj], aql, bkh[j2][nh], bkh[j2][nh + 2]);
            mma_bf16(F.a2[nj], akh, bqh[j2][nh], bqh[j2][nh + 2]);
            mma_bf16(F.a2[nj], akh, bql[j2][nh], bql[j2][nh + 2]);
            mma_bf16(F.a2[nj], akl, bqh[j2][nh], bqh[j2][nh + 2]);
        }
    }
}

__global__ __launch_bounds__(256, 2) void attn_kernel(
    const float* __restrict__ gates, float* __restrict__ attn_out)
{
    extern __shared__ char smraw[];
    __nv_bfloat16 (*sQh)[TLD]  = (__nv_bfloat16(*)[TLD])smraw;
    __nv_bfloat16 (*sQl)[TLD]  = sQh  + 64;
    __nv_bfloat16 (*sKqh)[TLD] = sQl  + 64;
    __nv_bfloat16 (*sKql)[TLD] = sKqh + 64;
    __nv_bfloat16 (*sKbh)[TLD] = sKql + 64;   // reused as Ph in pass B
    __nv_bfloat16 (*sKbl)[TLD] = sKbh + 64;   // reused as Pl
    __nv_bfloat16 (*sQbh)[TLD] = sKbl + 64;
    __nv_bfloat16 (*sQbl)[TLD] = sQbh + 64;
    __nv_bfloat16 (*sVh)[TLD]  = sQbl + 64;
    __nv_bfloat16 (*sVl)[TLD]  = sVh  + 64;
    float* sd    = (float*)(sVl + 64);        // 576
    float* sMred = sd + 576;                  // 128
    float* sSred = sMred + 128;               // 128

    __nv_bfloat16 (*sPh)[TLD] = sKbh, (*sPl)[TLD] = sKbl;

    int hh = blockIdx.y;
    int t0 = blockIdx.x * 64;
    int tid = threadIdx.x;
    int wid = tid >> 5, lane = tid & 31;
    int sb = t0 - 512; if (sb < 0) sb = 0;
    int L = t0 + 64 - sb;

    // ---- fused zero-fill of out-of-band attn region (fire-and-forget) ----
    {
        const float4 z4 = make_float4(0.f, 0.f, 0.f, 0.f);
        size_t rowbase = (size_t)hh * TT * TT + (size_t)t0 * TT;
        int leftq = sb >> 2;
        int right0 = t0 + 64;
        int rightq = (TT - right0) >> 2;
        for (int r = 0; r < 64; r++) {
            float4* bp = (float4*)(attn_out + rowbase + (size_t)r * TT);
            for (int c = tid; c < leftq; c += 256) bp[c] = z4;
            float4* rp4 = (float4*)(attn_out + rowbase + (size_t)r * TT + right0);
            for (int c = tid; c < rightq; c += 256) rp4[c] = z4;
        }
    }

    // gate softmax
    float g0 = gates[hh * 3 + 0], g1 = gates[hh * 3 + 1], g2 = gates[hh * 3 + 2];
    float gm = fmaxf(g0, fmaxf(g1, g2));
    float e0 = fast_exp(g0 - gm), e1 = fast_exp(g1 - gm), e2 = fast_exp(g2 - gm);
    float gi = 1.0f / (e0 + e1 + e2);
    float wstd = e0 * gi, wrec = e1 * gi, wdisc = e2 * gi;

    // load query-row tiles (Q,K hi/lo) via cp.async + d band
    for (int i = tid; i < 64 * 8; i += 256) {
        int row = i >> 3;
        int c8 = (i & 7) * 8;
        size_t off = (size_t)(t0 + row) * 768 + hh * 64 + c8;
        CPA16(smem_u32(&sQh[row][c8]),  g_Qh + off);
        CPA16(smem_u32(&sQl[row][c8]),  g_Ql + off);
        CPA16(smem_u32(&sKqh[row][c8]), g_Kh + off);
        CPA16(smem_u32(&sKql[row][c8]), g_Kl + off);
    }
    CPC();
    for (int i = tid; i < L; i += 256) sd[i] = g_d[hh * 4096 + sb + i];
    CPW0();

    int wm0 = (wid >> 1) * 16, wn0 = (wid & 1) * 32;
    int lr = lane & 15, lc = lane >> 4;
    int g = lane >> 2, t4 = lane & 3;
    int kt_lo = sb >> 6, kt_hi = t0 >> 6;
    int r0g = t0 + wm0 + g, r1g = r0g + 8;   // my two global rows

    LogitsFrag F;

    // ================= PASS A: online row max & sum ==================
    float m_run0 = -1e30f, m_run1 = -1e30f, s_run0 = 0.f, s_run1 = 0.f;

    for (int kt = kt_lo; kt <= kt_hi; kt++) {
        int s0 = kt * 64;
        __syncthreads();
        for (int i = tid; i < 64 * 8; i += 256) {
            int row = i >> 3;
            int c8 = (i & 7) * 8;
            size_t off = (size_t)(s0 + row) * 768 + hh * 64 + c8;
            CPA16(smem_u32(&sKbh[row][c8]), g_Kh + off);
            CPA16(smem_u32(&sKbl[row][c8]), g_Kl + off);
            CPA16(smem_u32(&sQbh[row][c8]), g_Qh + off);
            CPA16(smem_u32(&sQbl[row][c8]), g_Ql + off);
        }
        CPC(); CPW0();
        __syncthreads();

        logits_mma(sQh, sQl, sKqh, sKql, sKbh, sKbl, sQbh, sQbl, wm0, wn0, lr, lc, F);

        int soff = s0 - sb;
        float v[4][4];
        float vmax0 = -1e30f, vmax1 = -1e30f;
        #pragma unroll
        for (int nj = 0; nj < 4; nj++)
            #pragma unroll
            for (int q = 0; q < 4; q++) {
                int cl = wn0 + nj * 8 + t4 * 2 + (q & 1);
                int t = (q < 2) ? r0g : r1g;
                int s = s0 + cl;
                float vv;
                if (s <= t && (t - s) <= 512)
                    vv = (wstd * F.a1[nj][q] + wrec * F.a2[nj][q]) * 0.125f + wdisc * sd[soff + cl];
                else
                    vv = -1e30f;
                v[nj][q] = vv;
                if (q < 2) vmax0 = fmaxf(vmax0, vv); else vmax1 = fmaxf(vmax1, vv);
            }
        vmax0 = fmaxf(vmax0, __shfl_xor_sync(0xffffffffu, vmax0, 1));
        vmax0 = fmaxf(vmax0, __shfl_xor_sync(0xffffffffu, vmax0, 2));
        vmax1 = fmaxf(vmax1, __shfl_xor_sync(0xffffffffu, vmax1, 1));
        vmax1 = fmaxf(vmax1, __shfl_xor_sync(0xffffffffu, vmax1, 2));
        float mn0 = fmaxf(m_run0, vmax0), mn1 = fmaxf(m_run1, vmax1);
        float sum0 = 0.f, sum1 = 0.f;
        #pragma unroll
        for (int nj = 0; nj < 4; nj++)
            #pragma unroll
            for (int q = 0; q < 4; q++) {
                float e = fast_exp(v[nj][q] - ((q < 2) ? mn0 : mn1));
                if (q < 2) sum0 += e; else sum1 += e;
            }
        sum0 += __shfl_xor_sync(0xffffffffu, sum0, 1);
        sum0 += __shfl_xor_sync(0xffffffffu, sum0, 2);
        sum1 += __shfl_xor_sync(0xffffffffu, sum1, 1);
        sum1 += __shfl_xor_sync(0xffffffffu, sum1, 2);
        s_run0 = s_run0 * fast_exp(m_run0 - mn0) + sum0;
        s_run1 = s_run1 * fast_exp(m_run1 - mn1) + sum1;
        m_run0 = mn0; m_run1 = mn1;
    }

    // combine the two warps (wid, wid^1) that share rows
    if (t4 == 0) {
        sMred[wid * 16 + g]     = m_run0;
        sMred[wid * 16 + 8 + g] = m_run1;
        sSred[wid * 16 + g]     = s_run0;
        sSred[wid * 16 + 8 + g] = s_run1;
    }
    __syncthreads();
    float mf0, mf1, invs0, invs1;
    {
        int own = wid * 16, par = (wid ^ 1) * 16;
        float mA = sMred[own + g], mB = sMred[par + g];
        mf0 = fmaxf(mA, mB);
        float sf = sSred[own + g] * fast_exp(mA - mf0) + sSred[par + g] * fast_exp(mB - mf0);
        invs0 = 1.0f / sf;
        mA = sMred[own + 8 + g]; mB = sMred[par + 8 + g];
        mf1 = fmaxf(mA, mB);
        sf = sSred[own + 8 + g] * fast_exp(mA - mf1) + sSred[par + 8 + g] * fast_exp(mB - mf1);
        invs1 = 1.0f / sf;
    }

    // ================= PASS B: recompute, write attn, PV ==================
    float acc3[4][4];
    #pragma unroll
    for (int nj = 0; nj < 4; nj++)
        #pragma unroll
        for (int q = 0; q < 4; q++) acc3[nj][q] = 0.f;

    for (int kt = kt_lo; kt <= kt_hi; kt++) {
        int s0 = kt * 64;
        __syncthreads();
        // group 1: Kb/Qb ; group 2: V (into dedicated tiles)
        for (int i = tid; i < 64 * 8; i += 256) {
            int row = i >> 3;
            int c8 = (i & 7) * 8;
            size_t off = (size_t)(s0 + row) * 768 + hh * 64 + c8;
            CPA16(smem_u32(&sKbh[row][c8]), g_Kh + off);
            CPA16(smem_u32(&sKbl[row][c8]), g_Kl + off);
            CPA16(smem_u32(&sQbh[row][c8]), g_Qh + off);
            CPA16(smem_u32(&sQbl[row][c8]), g_Ql + off);
        }
        CPC();
        for (int i = tid; i < 64 * 8; i += 256) {
            int row = i >> 3;
            int c8 = (i & 7) * 8;
            size_t off = (size_t)(s0 + row) * 768 + hh * 64 + c8;
            CPA16(smem_u32(&sVh[row][c8]), g_Vh + off);
            CPA16(smem_u32(&sVl[row][c8]), g_Vl + off);
        }
        CPC();
        CPW1();   // Kb/Qb group done; V may still be in flight
        __syncthreads();

        logits_mma(sQh, sQl, sKqh, sKql, sKbh, sKbl, sQbh, sQbl, wm0, wn0, lr, lc, F);

        int soff = s0 - sb;
        float p[4][4];
        #pragma unroll
        for (int nj = 0; nj < 4; nj++)
            #pragma unroll
            for (int q = 0; q < 4; q++) {
                int cl = wn0 + nj * 8 + t4 * 2 + (q & 1);
                int t = (q < 2) ? r0g : r1g;
                int s = s0 + cl;
                float vv;
                if (s <= t && (t - s) <= 512)
                    vv = (wstd * F.a1[nj][q] + wrec * F.a2[nj][q]) * 0.125f + wdisc * sd[soff + cl];
                else
                    vv = -1e30f;
                p[nj][q] = fast_exp(vv - ((q < 2) ? mf0 : mf1)) * ((q < 2) ? invs0 : invs1);
            }

        // write normalized attn band directly from registers
        {
            size_t base = (size_t)hh * TT * TT;
            #pragma unroll
            for (int nj = 0; nj < 4; nj++) {
                int cg = s0 + wn0 + nj * 8 + t4 * 2;
                *(float2*)(attn_out + base + (size_t)r0g * TT + cg) = make_float2(p[nj][0], p[nj][1]);
                *(float2*)(attn_out + base + (size_t)r1g * TT + cg) = make_float2(p[nj][2], p[nj][3]);
            }
        }

        __syncthreads();   // all warps done reading Kb/Qb -> safe to overwrite as P

        // stage normalized P as bf16 hi/lo into sKb slots
        #pragma unroll
        for (int nj = 0; nj < 4; nj++) {
            int c = wn0 + nj * 8 + t4 * 2;
            float v0 = p[nj][0], v1 = p[nj][1];
            float h0 = __bfloat162float(__float2bfloat16_rn(v0));
            float h1 = __bfloat162float(__float2bfloat16_rn(v1));
            *(u32*)&sPh[wm0 + g][c] = pack_bf16x2(v0, v1);
            *(u32*)&sPl[wm0 + g][c] = pack_bf16x2(v0 - h0, v1 - h1);
            v0 = p[nj][2]; v1 = p[nj][3];
            h0 = __bfloat162float(__float2bfloat16_rn(v0));
            h1 = __bfloat162float(__float2bfloat16_rn(v1));
            *(u32*)&sPh[wm0 + 8 + g][c] = pack_bf16x2(v0, v1);
            *(u32*)&sPl[wm0 + 8 + g][c] = pack_bf16x2(v0 - h0, v1 - h1);
        }
        CPW0();   // V arrived
        __syncthreads();

        // PV MMA: A = P (normalized), B = V^T
        #pragma unroll
        for (int kk = 0; kk < 64; kk += 16) {
            u32 aph[4], apl[4];
            u32 adr = smem_u32(&sPh[wm0 + lr][kk + lc * 8]);
            ldsm_x4(adr, aph[0], aph[1], aph[2], aph[3]);
            adr = smem_u32(&sPl[wm0 + lr][kk + lc * 8]);
            ldsm_x4(adr, apl[0], apl[1], apl[2], apl[3]);
            u32 bvh[2][4], bvl[2][4];
            #pragma unroll
            for (int nj2 = 0; nj2 < 2; nj2++) {
                adr = smem_u32(&sVh[kk + lr][wn0 + nj2 * 16 + lc * 8]);
                ldsm_x4t(adr, bvh[nj2][0], bvh[nj2][1], bvh[nj2][2], bvh[nj2][3]);
                adr = smem_u32(&sVl[kk + lr][wn0 + nj2 * 16 + lc * 8]);
                ldsm_x4t(adr, bvl[nj2][0], bvl[nj2][1], bvl[nj2][2], bvl[nj2][3]);
            }
            #pragma unroll
            for (int nj = 0; nj < 4; nj++) {
                int j2 = nj >> 1, hf = (nj & 1) * 2;
                mma_bf16(acc3[nj], aph, bvh[j2][hf], bvh[j2][hf + 1]);
                mma_bf16(acc3[nj], aph, bvl[j2][hf], bvl[j2][hf + 1]);
                mma_bf16(acc3[nj], apl, bvh[j2][hf], bvh[j2][hf + 1]);
            }
        }
    }

    // ctx epilogue (already normalized): write bf16 hi/lo
    #pragma unroll
    for (int nj = 0; nj < 4; nj++)
        #pragma unroll
        for (int rr = 0; rr < 2; rr++) {
            int rl = wm0 + g + rr * 8;
            float v0 = acc3[nj][rr * 2];
            float v1 = acc3[nj][rr * 2 + 1];
            float h0 = __bfloat162float(__float2bfloat16_rn(v0));
            float h1 = __bfloat162float(__float2bfloat16_rn(v1));
            size_t off = (size_t)(t0 + rl) * 768 + hh * 64 + wn0 + nj * 8 + t4 * 2;
            *(u32*)(g_ch + off) = pack_bf16x2(v0, v1);
            *(u32*)(g_cl + off) = pack_bf16x2(v0 - h0, v1 - h1);
        }
}

// ---------------- launch ----------------------------------------------------
extern "C" void kernel_launch(void* const* d_in, const int* in_sizes, int n_in,
                              void* d_out, int out_size)
{
    const float* x     = (const float*)d_in[0];
    const float* Wq    = (const float*)d_in[1];
    const float* Wk    = (const float*)d_in[2];
    const float* Wv    = (const float*)d_in[3];
    const float* Wo    = (const float*)d_in[4];
    const float* gates = (const float*)d_in[5];
    const float* u     = (const float*)d_in[6];
    float* out  = (float*)d_out;
    float* attn = out + OUT_ELEMS;

    cudaFuncSetAttribute(attn_kernel, cudaFuncAttributeMaxDynamicSharedMemorySize, ATT_SMEM);
    cudaFuncSetAttribute(bgemm_kernel, cudaFuncAttributeMaxDynamicSharedMemorySize, GEMM_SMEM);

    // split fp32 -> bf16 hi/lo (one launch)
    cvt_kernel<<<(CVT_TOTAL + 255)/256, 256>>>(x, Wq, Wk, Wv, Wo);

    // QKV projections: one launch, z = wsel
    dim3 gq(12, 32, 3);
    bgemm_kernel<<<gq, 256, GEMM_SMEM>>>(nullptr, -1);

    // d bias from K (hi+lo reconstruct)
    dbias_kernel<<<12, 1024>>>(u);

    // banded gated attention (recompute softmax, 2 CTAs/SM)
    dim3 ga(64, 12, 1);
    attn_kernel<<<ga, 256, ATT_SMEM>>>(gates, attn);

    // output projection (fp32 out)
    dim3 go(12, 32, 1);
    bgemm_kernel<<<go, 256, GEMM_SMEM>>>(out, 3);
}

// round 17
// speedup vs baseline: 1.0037x; 1.0037x over previous
#include <cuda_runtime.h>
#include <cuda_bf16.h>
#include <math.h>

#define TT 4096
#define EE 768
#define HH 12
#define DD 64
#define WIN 512
#define OUT_ELEMS (TT*EE)                 // 3145728
#define ATTN_ELEMS ((size_t)HH*TT*TT)     // 201326592

typedef unsigned long long ull;
typedef unsigned int u32;

// cp.async helpers (16B)
#define CPA16(dst, src) asm volatile("cp.async.cg.shared.global [%0], [%1], 16;" :: "r"(dst), "l"(src))
#define CPC()  asm volatile("cp.async.commit_group;")
#define CPW0() asm volatile("cp.async.wait_group 0;" ::: "memory")
#define CPW1() asm volatile("cp.async.wait_group 1;" ::: "memory")

// ---------------- scratch (device globals: allocation-free) ----------------
__device__ __align__(16) float g_d[HH*TT];

// bf16 two-term split buffers
__device__ __align__(16) __nv_bfloat16 g_xh[TT*EE], g_xl[TT*EE];
__device__ __align__(16) __nv_bfloat16 g_Wh[4][EE*EE], g_Wl[4][EE*EE];
__device__ __align__(16) __nv_bfloat16 g_Qh[TT*EE], g_Ql[TT*EE];
__device__ __align__(16) __nv_bfloat16 g_Kh[TT*EE], g_Kl[TT*EE];
__device__ __align__(16) __nv_bfloat16 g_Vh[TT*EE], g_Vl[TT*EE];
__device__ __align__(16) __nv_bfloat16 g_ch[TT*EE], g_cl[TT*EE];   // ctx hi/lo

// ---------------- helpers ----------------------------------------------------
__device__ __forceinline__ u32 pack_bf16x2(float a, float b) {
    __nv_bfloat16 ha = __float2bfloat16_rn(a), hb = __float2bfloat16_rn(b);
    return ((u32)__bfloat16_as_ushort(hb) << 16) | __bfloat16_as_ushort(ha);
}
// fast exp on FMA pipe: exp(x) = 2^(x*log2e), poly deg-5, ~2e-7 rel err
__device__ __forceinline__ float fast_exp(float x) {
    float y = fmaxf(x * 1.4426950408889634f, -126.0f);
    float n = floorf(y);
    float f = y - n;
    float p = 1.8775767e-3f;
    p = fmaf(p, f, 8.9893397e-3f);
    p = fmaf(p, f, 5.5826318e-2f);
    p = fmaf(p, f, 2.4015361e-1f);
    p = fmaf(p, f, 6.9315308e-1f);
    p = fmaf(p, f, 1.0f);
    float s = __int_as_float(((int)n + 127) << 23);
    return p * s;
}

// ---------------- fp32 -> bf16 hi/lo split (single fused launch) ------------
#define XN4 (OUT_ELEMS/4)          // 786432
#define WN4 (EE*EE/4)              // 147456
#define CVT_TOTAL (XN4 + 4*WN4)    // 1376256
__global__ __launch_bounds__(256) void cvt_kernel(
    const float* __restrict__ x,  const float* __restrict__ Wq,
    const float* __restrict__ Wk, const float* __restrict__ Wv,
    const float* __restrict__ Wo)
{
    int i = blockIdx.x * 256 + threadIdx.x;
    if (i >= CVT_TOTAL) return;
    const float* src; __nv_bfloat16 *hi, *lo; int idx;
    if (i < XN4) { src = x; hi = g_xh; lo = g_xl; idx = i; }
    else {
        int j = i - XN4;
        int w = j / WN4;
        idx = j - w * WN4;
        src = (w == 0) ? Wq : (w == 1) ? Wk : (w == 2) ? Wv : Wo;
        hi = g_Wh[w]; lo = g_Wl[w];
    }
    float4 v = ((const float4*)src)[idx];
    float h0f = __bfloat162float(__float2bfloat16_rn(v.x));
    float h1f = __bfloat162float(__float2bfloat16_rn(v.y));
    float h2f = __bfloat162float(__float2bfloat16_rn(v.z));
    float h3f = __bfloat162float(__float2bfloat16_rn(v.w));
    uint2 hp, lp;
    hp.x = pack_bf16x2(v.x, v.y);
    hp.y = pack_bf16x2(v.z, v.w);
    lp.x = pack_bf16x2(v.x - h0f, v.y - h1f);
    lp.y = pack_bf16x2(v.z - h2f, v.w - h3f);
    ((uint2*)hi)[idx] = hp;
    ((uint2*)lo)[idx] = lp;
}

// ---------------- mma helpers ------------------------------------------------
__device__ __forceinline__ u32 smem_u32(const void* p) {
    return (u32)__cvta_generic_to_shared(p);
}
__device__ __forceinline__ void ldsm_x4(u32 addr, u32& r0, u32& r1, u32& r2, u32& r3) {
    asm volatile("ldmatrix.sync.aligned.m8n8.x4.shared.b16 {%0,%1,%2,%3}, [%4];"
        : "=r"(r0), "=r"(r1), "=r"(r2), "=r"(r3) : "r"(addr));
}
__device__ __forceinline__ void ldsm_x4t(u32 addr, u32& r0, u32& r1, u32& r2, u32& r3) {
    asm volatile("ldmatrix.sync.aligned.m8n8.x4.trans.shared.b16 {%0,%1,%2,%3}, [%4];"
        : "=r"(r0), "=r"(r1), "=r"(r2), "=r"(r3) : "r"(addr));
}
__device__ __forceinline__ void mma_bf16(float* d, const u32* a, u32 b0, u32 b1) {
    asm volatile(
        "mma.sync.aligned.m16n8k16.row.col.f32.bf16.bf16.f32 "
        "{%0,%1,%2,%3}, {%4,%5,%6,%7}, {%8,%9}, {%0,%1,%2,%3};"
        : "+f"(d[0]), "+f"(d[1]), "+f"(d[2]), "+f"(d[3])
        : "r"(a[0]), "r"(a[1]), "r"(a[2]), "r"(a[3]), "r"(b0), "r"(b1));
}

// ---------------- split-bf16 GEMM, cp.async double-buffered -----------------
#define LDA 40
#define LDB 72
#define A_BUF (128*LDA)
#define B_BUF (32*LDB)
#define GEMM_SMEM ((2*A_BUF*2 + 2*B_BUF*2) * 2)   // 59392 bytes
#define NKI 24
__global__ __launch_bounds__(256) void bgemm_kernel(float* __restrict__ Cext, int wsel)
{
    if (wsel < 0) wsel = blockIdx.z;
    const __nv_bfloat16 *Ah, *Al;
    const __nv_bfloat16 *Bh = g_Wh[wsel], *Bl = g_Wl[wsel];
    __nv_bfloat16 *Ch = nullptr, *Cl = nullptr;
    if (wsel < 3) {
        Ah = g_xh; Al = g_xl;
        Ch = (wsel == 0) ? g_Qh : (wsel == 1) ? g_Kh : g_Vh;
        Cl = (wsel == 0) ? g_Ql : (wsel == 1) ? g_Kl : g_Vl;
    } else {
        Ah = g_ch; Al = g_cl;
    }

    extern __shared__ __nv_bfloat16 smb[];
    __nv_bfloat16* bAh = smb;
    __nv_bfloat16* bAl = bAh + 2 * A_BUF;
    __nv_bfloat16* bBh = bAl + 2 * A_BUF;
    __nv_bfloat16* bBl = bBh + 2 * B_BUF;

    int tid = threadIdx.x;
    int wid = tid >> 5, lane = tid & 31;
    int m0 = blockIdx.y * 128, n0 = blockIdx.x * 64;
    int wm0 = (wid >> 1) * 32, wn0 = (wid & 1) * 32;
    int lr = lane & 15, lc = lane >> 4;

    int ar0 = tid >> 2,            akc = (tid & 3) * 8;
    int ar1 = (tid + 256) >> 2,    akc1 = ((tid + 256) & 3) * 8;
    int brow = tid >> 3,           bnc = (tid & 7) * 8;

    float acc[2][4][4];
    #pragma unroll
    for (int mi = 0; mi < 2; mi++)
        #pragma unroll
        for (int nj = 0; nj < 4; nj++)
            #pragma unroll
            for (int q = 0; q < 4; q++) acc[mi][nj][q] = 0.f;

    {
        int k0 = 0;
        CPA16(smem_u32(bAh + ar0 * LDA + akc),  Ah + (size_t)(m0 + ar0) * 768 + k0 + akc);
        CPA16(smem_u32(bAh + ar1 * LDA + akc1), Ah + (size_t)(m0 + ar1) * 768 + k0 + akc1);
        CPA16(smem_u32(bAl + ar0 * LDA + akc),  Al + (size_t)(m0 + ar0) * 768 + k0 + akc);
        CPA16(smem_u32(bAl + ar1 * LDA + akc1), Al + (size_t)(m0 + ar1) * 768 + k0 + akc1);
        CPA16(smem_u32(bBh + brow * LDB + bnc), Bh + (size_t)(k0 + brow) * 768 + n0 + bnc);
        CPA16(smem_u32(bBl + brow * LDB + bnc), Bl + (size_t)(k0 + brow) * 768 + n0 + bnc);
        CPC();
    }

    int buf = 0;
    for (int ki = 0; ki < NKI; ki++) {
        CPW0();
        __syncthreads();
        if (ki + 1 < NKI) {
            int k0 = (ki + 1) * 32;
            int ob = (buf ^ 1);
            __nv_bfloat16* dAh = bAh + ob * A_BUF;
            __nv_bfloat16* dAl = bAl + ob * A_BUF;
            __nv_bfloat16* dBh = bBh + ob * B_BUF;
            __nv_bfloat16* dBl = bBl + ob * B_BUF;
            CPA16(smem_u32(dAh + ar0 * LDA + akc),  Ah + (size_t)(m0 + ar0) * 768 + k0 + akc);
            CPA16(smem_u32(dAh + ar1 * LDA + akc1), Ah + (size_t)(m0 + ar1) * 768 + k0 + akc1);
            CPA16(smem_u32(dAl + ar0 * LDA + akc),  Al + (size_t)(m0 + ar0) * 768 + k0 + akc);
            CPA16(smem_u32(dAl + ar1 * LDA + akc1), Al + (size_t)(m0 + ar1) * 768 + k0 + akc1);
            CPA16(smem_u32(dBh + brow * LDB + bnc), Bh + (size_t)(k0 + brow) * 768 + n0 + bnc);
            CPA16(smem_u32(dBl + brow * LDB + bnc), Bl + (size_t)(k0 + brow) * 768 + n0 + bnc);
            CPC();
        }

        const __nv_bfloat16* cAh = bAh + buf * A_BUF;
        const __nv_bfloat16* cAl = bAl + buf * A_BUF;
        const __nv_bfloat16* cBh = bBh + buf * B_BUF;
        const __nv_bfloat16* cBl = bBl + buf * B_BUF;

        #pragma unroll
        for (int kk = 0; kk < 32; kk += 16) {
            u32 ah[2][4], al[2][4], bh[2][4], bl[2][4];
            #pragma unroll
            for (int mi = 0; mi < 2; mi++) {
                u32 adr = smem_u32(cAh + (wm0 + mi * 16 + lr) * LDA + kk + lc * 8);
                ldsm_x4(adr, ah[mi][0], ah[mi][1], ah[mi][2], ah[mi][3]);
                adr = smem_u32(cAl + (wm0 + mi * 16 + lr) * LDA + kk + lc * 8);
                ldsm_x4(adr, al[mi][0], al[mi][1], al[mi][2], al[mi][3]);
            }
            #pragma unroll
            for (int nj2 = 0; nj2 < 2; nj2++) {
                u32 adr = smem_u32(cBh + (kk + lr) * LDB + wn0 + nj2 * 16 + lc * 8);
                ldsm_x4t(adr, bh[nj2][0], bh[nj2][1], bh[nj2][2], bh[nj2][3]);
                adr = smem_u32(cBl + (kk + lr) * LDB + wn0 + nj2 * 16 + lc * 8);
                ldsm_x4t(adr, bl[nj2][0], bl[nj2][1], bl[nj2][2], bl[nj2][3]);
            }
            #pragma unroll
            for (int mi = 0; mi < 2; mi++)
                #pragma unroll
                for (int nj = 0; nj < 4; nj++) {
                    int j2 = nj >> 1, hf = (nj & 1) * 2;
                    mma_bf16(acc[mi][nj], ah[mi], bh[j2][hf], bh[j2][hf + 1]);
                    mma_bf16(acc[mi][nj], ah[mi], bl[j2][hf], bl[j2][hf + 1]);
                    mma_bf16(acc[mi][nj], al[mi], bh[j2][hf], bh[j2][hf + 1]);
                }
        }
        buf ^= 1;
        __syncthreads();
    }

    int g = lane >> 2, t4 = lane & 3;
    #pragma unroll
    for (int mi = 0; mi < 2; mi++)
        #pragma unroll
        for (int nj = 0; nj < 4; nj++) {
            int row = m0 + wm0 + mi * 16 + g;
            int col = n0 + wn0 + nj * 8 + t4 * 2;
            if (wsel == 3) {
                *(float2*)&Cext[(size_t)row * 768 + col] =
                    make_float2(acc[mi][nj][0], acc[mi][nj][1]);
                *(float2*)&Cext[(size_t)(row + 8) * 768 + col] =
                    make_float2(acc[mi][nj][2], acc[mi][nj][3]);
            } else {
                #pragma unroll
                for (int rr = 0; rr < 2; rr++) {
                    float v0 = acc[mi][nj][rr * 2], v1 = acc[mi][nj][rr * 2 + 1];
                    float h0 = __bfloat162float(__float2bfloat16_rn(v0));
                    float h1 = __bfloat162float(__float2bfloat16_rn(v1));
                    size_t off = (size_t)(row + rr * 8) * 768 + col;
                    *(u32*)(Ch + off) = pack_bf16x2(v0, v1);
                    *(u32*)(Cl + off) = pack_bf16x2(v0 - h0, v1 - h1);
                }
            }
        }
}

// ---------------- d bias -----------------------------------------------------
__global__ __launch_bounds__(1024) void dbias_kernel(const float* __restrict__ u)
{
    int h = blockIdx.x, tid = threadIdx.x;
    __shared__ float su[64];
    __shared__ float red[32];
    if (tid < 64) su[tid] = u[h * 64 + tid];
    __syncthreads();

    float vals[4];
    float lsum = 0.f;
    #pragma unroll
    for (int j = 0; j < 4; j++) {
        int t = j * 1024 + tid;
        const __nv_bfloat162* kh = (const __nv_bfloat162*)(g_Kh + (size_t)t * 768 + h * 64);
        const __nv_bfloat162* kl = (const __nv_bfloat162*)(g_Kl + (size_t)t * 768 + h * 64);
        float dot = 0.f;
        #pragma unroll
        for (int q = 0; q < 32; q++) {
            float2 hv = __bfloat1622float2(kh[q]);
            float2 lv = __bfloat1622float2(kl[q]);
            dot += (hv.x + lv.x) * su[q * 2] + (hv.y + lv.y) * su[q * 2 + 1];
        }
        vals[j] = dot;
        lsum += dot;
    }
    #pragma unroll
    for (int o = 16; o > 0; o >>= 1) lsum += __shfl_xor_sync(0xffffffffu, lsum, o);
    if ((tid & 31) == 0) red[tid >> 5] = lsum;
    __syncthreads();
    if (tid < 32) {
        float v = red[tid];
        #pragma unroll
        for (int o = 16; o > 0; o >>= 1) v += __shfl_xor_sync(0xffffffffu, v, o);
        if (tid == 0) red[0] = v * (1.0f / 4096.0f);
    }
    __syncthreads();
    float mean = red[0];
    #pragma unroll
    for (int j = 0; j < 4; j++)
        g_d[h * 4096 + j * 1024 + tid] = vals[j] - mean;
}

// ---------------- attention: recompute-softmax, no sL band buffer -----------
// smem: 10 bf16 tiles [64][72] (Q,K query hi/lo; Kb,Qb key hi/lo (reused as
// Ph,Pl); V hi/lo) + sd + (m,s) reduction scratch = 95.5 KB -> 2 CTAs/SM.
#define TLD 72
#define TILE_B (64*TLD)           // bf16 elements per tile
#define ATT_SMEM (10*TILE_B*2 + 576*4 + 256*4)

struct LogitsFrag { float a1[4][4]; float a2[4][4]; };

__device__ __forceinline__ void logits_mma(
    const __nv_bfloat16 (*sQh)[TLD], const __nv_bfloat16 (*sQl)[TLD],
    const __nv_bfloat16 (*sKqh)[TLD], const __nv_bfloat16 (*sKql)[TLD],
    const __nv_bfloat16 (*sKbh)[TLD], const __nv_bfloat16 (*sKbl)[TLD],
    const __nv_bfloat16 (*sQbh)[TLD], const __nv_bfloat16 (*sQbl)[TLD],
    int wm0, int wn0, int lr, int lc, LogitsFrag& F)
{
    #pragma unroll
    for (int nj = 0; nj < 4; nj++)
        #pragma unroll
        for (int q = 0; q < 4; q++) { F.a1[nj][q] = 0.f; F.a2[nj][q] = 0.f; }

    #pragma unroll
    for (int kk = 0; kk < 64; kk += 16) {
        u32 aqh[4], aql[4], akh[4], akl[4];
        u32 adr = smem_u32(&sQh[wm0 + lr][kk + lc * 8]);
        ldsm_x4(adr, aqh[0], aqh[1], aqh[2], aqh[3]);
        adr = smem_u32(&sQl[wm0 + lr][kk + lc * 8]);
        ldsm_x4(adr, aql[0], aql[1], aql[2], aql[3]);
        adr = smem_u32(&sKqh[wm0 + lr][kk + lc * 8]);
        ldsm_x4(adr, akh[0], akh[1], akh[2], akh[3]);
        adr = smem_u32(&sKql[wm0 + lr][kk + lc * 8]);
        ldsm_x4(adr, akl[0], akl[1], akl[2], akl[3]);

        u32 bkh[2][4], bkl[2][4], bqh[2][4], bql[2][4];
        #pragma unroll
        for (int nj2 = 0; nj2 < 2; nj2++) {
            adr = smem_u32(&sKbh[wn0 + nj2 * 16 + lr][kk + lc * 8]);
            ldsm_x4(adr, bkh[nj2][0], bkh[nj2][1], bkh[nj2][2], bkh[nj2][3]);
            adr = smem_u32(&sKbl[wn0 + nj2 * 16 + lr][kk + lc * 8]);
            ldsm_x4(adr, bkl[nj2][0], bkl[nj2][1], bkl[nj2][2], bkl[nj2][3]);
            adr = smem_u32(&sQbh[wn0 + nj2 * 16 + lr][kk + lc * 8]);
            ldsm_x4(adr, bqh[nj2][0], bqh[nj2][1], bqh[nj2][2], bqh[nj2][3]);
            adr = smem_u32(&sQbl[wn0 + nj2 * 16 + lr][kk + lc * 8]);
            ldsm_x4(adr, bql[nj2][0], bql[nj2][1], bql[nj2][2], bql[nj2][3]);
        }
        #pragma unroll
        for (int nj = 0; nj < 4; nj++) {
            int j2 = nj >> 1, nh = nj & 1;
            mma_bf16(F.a1[nj], aqh, bkh[j2][nh], bkh[j2][nh + 2]);
            mma_bf16(F.a1[nj], aqh, bkl[j2][nh], bkl[j2][nh + 2]);
            mma_bf16(F.a1[nj], aql, bkh[j2][nh], bkh[j2][nh + 2]);
            mma_bf16(F.a2[nj], akh, bqh[j2][nh], bqh[j2][nh + 2]);
            mma_bf16(F.a2[nj], akh, bql[j2][nh], bql[j2][nh + 2]);
            mma_bf16(F.a2[nj], akl, bqh[j2][nh], bqh[j2][nh + 2]);
        }
    }
}

__global__ __launch_bounds__(256, 2) void attn_kernel(
    const float* __restrict__ gates, float* __restrict__ attn_out)
{
    extern __shared__ char smraw[];
    __nv_bfloat16 (*sQh)[TLD]  = (__nv_bfloat16(*)[TLD])smraw;
    __nv_bfloat16 (*sQl)[TLD]  = sQh  + 64;
    __nv_bfloat16 (*sKqh)[TLD] = sQl  + 64;
    __nv_bfloat16 (*sKql)[TLD] = sKqh + 64;
    __nv_bfloat16 (*sKbh)[TLD] = sKql + 64;   // reused as Ph in pass B
    __nv_bfloat16 (*sKbl)[TLD] = sKbh + 64;   // reused as Pl
    __nv_bfloat16 (*sQbh)[TLD] = sKbl + 64;
    __nv_bfloat16 (*sQbl)[TLD] = sQbh + 64;
    __nv_bfloat16 (*sVh)[TLD]  = sQbl + 64;
    __nv_bfloat16 (*sVl)[TLD]  = sVh  + 64;
    float* sd    = (float*)(sVl + 64);        // 576
    float* sMred = sd + 576;                  // 128
    float* sSred = sMred + 128;               // 128

    __nv_bfloat16 (*sPh)[TLD] = sKbh, (*sPl)[TLD] = sKbl;

    int hh = blockIdx.y;
    int t0 = blockIdx.x * 64;
    int tid = threadIdx.x;
    int wid = tid >> 5, lane = tid & 31;
    int sb = t0 - 512; if (sb < 0) sb = 0;
    int L = t0 + 64 - sb;

    // ---- fused zero-fill of out-of-band attn region (fire-and-forget) ----
    {
        const float4 z4 = make_float4(0.f, 0.f, 0.f, 0.f);
        size_t rowbase = (size_t)hh * TT * TT + (size_t)t0 * TT;
        int leftq = sb >> 2;
        int right0 = t0 + 64;
        int rightq = (TT - right0) >> 2;
        for (int r = 0; r < 64; r++) {
            float4* bp = (float4*)(attn_out + rowbase + (size_t)r * TT);
            for (int c = tid; c < leftq; c += 256) bp[c] = z4;
            float4* rp4 = (float4*)(attn_out + rowbase + (size_t)r * TT + right0);
            for (int c = tid; c < rightq; c += 256) rp4[c] = z4;
        }
    }

    // gate softmax
    float g0 = gates[hh * 3 + 0], g1 = gates[hh * 3 + 1], g2 = gates[hh * 3 + 2];
    float gm = fmaxf(g0, fmaxf(g1, g2));
    float e0 = fast_exp(g0 - gm), e1 = fast_exp(g1 - gm), e2 = fast_exp(g2 - gm);
    float gi = 1.0f / (e0 + e1 + e2);
    float wstd = e0 * gi, wrec = e1 * gi, wdisc = e2 * gi;

    // load query-row tiles (Q,K hi/lo) via cp.async + d band
    for (int i = tid; i < 64 * 8; i += 256) {
        int row = i >> 3;
        int c8 = (i & 7) * 8;
        size_t off = (size_t)(t0 + row) * 768 + hh * 64 + c8;
        CPA16(smem_u32(&sQh[row][c8]),  g_Qh + off);
        CPA16(smem_u32(&sQl[row][c8]),  g_Ql + off);
        CPA16(smem_u32(&sKqh[row][c8]), g_Kh + off);
        CPA16(smem_u32(&sKql[row][c8]), g_Kl + off);
    }
    CPC();
    for (int i = tid; i < L; i += 256) sd[i] = g_d[hh * 4096 + sb + i];
    CPW0();

    int wm0 = (wid >> 1) * 16, wn0 = (wid & 1) * 32;
    int lr = lane & 15, lc = lane >> 4;
    int g = lane >> 2, t4 = lane & 3;
    int kt_lo = sb >> 6, kt_hi = t0 >> 6;
    int r0g = t0 + wm0 + g, r1g = r0g + 8;   // my two global rows

    LogitsFrag F;

    // ================= PASS A: online row max & sum ==================
    float m_run0 = -1e30f, m_run1 = -1e30f, s_run0 = 0.f, s_run1 = 0.f;

    for (int kt = kt_lo; kt <= kt_hi; kt++) {
        int s0 = kt * 64;
        __syncthreads();
        for (int i = tid; i < 64 * 8; i += 256) {
            int row = i >> 3;
            int c8 = (i & 7) * 8;
            size_t off = (size_t)(s0 + row) * 768 + hh * 64 + c8;
            CPA16(smem_u32(&sKbh[row][c8]), g_Kh + off);
            CPA16(smem_u32(&sKbl[row][c8]), g_Kl + off);
            CPA16(smem_u32(&sQbh[row][c8]), g_Qh + off);
            CPA16(smem_u32(&sQbl[row][c8]), g_Ql + off);
        }
        CPC(); CPW0();
        __syncthreads();

        logits_mma(sQh, sQl, sKqh, sKql, sKbh, sKbl, sQbh, sQbl, wm0, wn0, lr, lc, F);

        int soff = s0 - sb;
        float v[4][4];
        float vmax0 = -1e30f, vmax1 = -1e30f;
        #pragma unroll
        for (int nj = 0; nj < 4; nj++)
            #pragma unroll
            for (int q = 0; q < 4; q++) {
                int cl = wn0 + nj * 8 + t4 * 2 + (q & 1);
                int t = (q < 2) ? r0g : r1g;
                int s = s0 + cl;
                float vv;
                if (s <= t && (t - s) <= 512)
                    vv = (wstd * F.a1[nj][q] + wrec * F.a2[nj][q]) * 0.125f + wdisc * sd[soff + cl];
                else
                    vv = -1e30f;
                v[nj][q] = vv;
                if (q < 2) vmax0 = fmaxf(vmax0, vv); else vmax1 = fmaxf(vmax1, vv);
            }
        vmax0 = fmaxf(vmax0, __shfl_xor_sync(0xffffffffu, vmax0, 1));
        vmax0 = fmaxf(vmax0, __shfl_xor_sync(0xffffffffu, vmax0, 2));
        vmax1 = fmaxf(vmax1, __shfl_xor_sync(0xffffffffu, vmax1, 1));
        vmax1 = fmaxf(vmax1, __shfl_xor_sync(0xffffffffu, vmax1, 2));
        float mn0 = fmaxf(m_run0, vmax0), mn1 = fmaxf(m_run1, vmax1);
        float sum0 = 0.f, sum1 = 0.f;
        #pragma unroll
        for (int nj = 0; nj < 4; nj++)
            #pragma unroll
            for (int q = 0; q < 4; q++) {
                float e = fast_exp(v[nj][q] - ((q < 2) ? mn0 : mn1));
                if (q < 2) sum0 += e; else sum1 += e;
            }
        sum0 += __shfl_xor_sync(0xffffffffu, sum0, 1);
        sum0 += __shfl_xor_sync(0xffffffffu, sum0, 2);
        sum1 += __shfl_xor_sync(0xffffffffu, sum1, 1);
        sum1 += __shfl_xor_sync(0xffffffffu, sum1, 2);
        s_run0 = s_run0 * fast_exp(m_run0 - mn0) + sum0;
        s_run1 = s_run1 * fast_exp(m_run1 - mn1) + sum1;
        m_run0 = mn0; m_run1 = mn1;
    }

    // combine the two warps (wid, wid^1) that share rows
    if (t4 == 0) {
        sMred[wid * 16 + g]     = m_run0;
        sMred[wid * 16 + 8 + g] = m_run1;
        sSred[wid * 16 + g]     = s_run0;
        sSred[wid * 16 + 8 + g] = s_run1;
    }
    __syncthreads();
    float mf0, mf1, invs0, invs1;
    {
        int own = wid * 16, par = (wid ^ 1) * 16;
        float mA = sMred[own + g], mB = sMred[par + g];
        mf0 = fmaxf(mA, mB);
        float sf = sSred[own + g] * fast_exp(mA - mf0) + sSred[par + g] * fast_exp(mB - mf0);
        invs0 = 1.0f / sf;
        mA = sMred[own + 8 + g]; mB = sMred[par + 8 + g];
        mf1 = fmaxf(mA, mB);
        sf = sSred[own + 8 + g] * fast_exp(mA - mf1) + sSred[par + 8 + g] * fast_exp(mB - mf1);
        invs1 = 1.0f / sf;
    }

    // ================= PASS B: recompute, write attn, PV ==================
    float acc3[4][4];
    #pragma unroll
    for (int nj = 0; nj < 4; nj++)
        #pragma unroll
        for (int q = 0; q < 4; q++) acc3[nj][q] = 0.f;

    for (int kt = kt_lo; kt <= kt_hi; kt++) {
        int s0 = kt * 64;
        __syncthreads();
        // group 1: Kb/Qb ; group 2: V (into dedicated tiles)
        for (int i = tid; i < 64 * 8; i += 256) {
            int row = i >> 3;
            int c8 = (i & 7) * 8;
            size_t off = (size_t)(s0 + row) * 768 + hh * 64 + c8;
            CPA16(smem_u32(&sKbh[row][c8]), g_Kh + off);
            CPA16(smem_u32(&sKbl[row][c8]), g_Kl + off);
            CPA16(smem_u32(&sQbh[row][c8]), g_Qh + off);
            CPA16(smem_u32(&sQbl[row][c8]), g_Ql + off);
        }
        CPC();
        for (int i = tid; i < 64 * 8; i += 256) {
            int row = i >> 3;
            int c8 = (i & 7) * 8;
            size_t off = (size_t)(s0 + row) * 768 + hh * 64 + c8;
            CPA16(smem_u32(&sVh[row][c8]), g_Vh + off);
            CPA16(smem_u32(&sVl[row][c8]), g_Vl + off);
        }
        CPC();
        CPW1();   // Kb/Qb group done; V may still be in flight
        __syncthreads();

        logits_mma(sQh, sQl, sKqh, sKql, sKbh, sKbl, sQbh, sQbl, wm0, wn0, lr, lc, F);

        int soff = s0 - sb;
        float p[4][4];
        #pragma unroll
        for (int nj = 0; nj < 4; nj++)
            #pragma unroll
            for (int q = 0; q < 4; q++) {
                int cl = wn0 + nj * 8 + t4 * 2 + (q & 1);
                int t = (q < 2) ? r0g : r1g;
                int s = s0 + cl;
                float vv;
                if (s <= t && (t - s) <= 512)
                    vv = (wstd * F.a1[nj][q] + wrec * F.a2[nj][q]) * 0.125f + wdisc * sd[soff + cl];
                else
                    vv = -1e30f;
                p[nj][q] = fast_exp(vv - ((q < 2) ? mf0 : mf1)) * ((q < 2) ? invs0 : invs1);
            }

        // write normalized attn band directly from registers
        {
            size_t base = (size_t)hh * TT * TT;
            #pragma unroll
            for (int nj = 0; nj < 4; nj++) {
                int cg = s0 + wn0 + nj * 8 + t4 * 2;
                *(float2*)(attn_out + base + (size_t)r0g * TT + cg) = make_float2(p[nj][0], p[nj][1]);
                *(float2*)(attn_out + base + (size_t)r1g * TT + cg) = make_float2(p[nj][2], p[nj][3]);
            }
        }

        __syncthreads();   // all warps done reading Kb/Qb -> safe to overwrite as P

        // stage normalized P as bf16 hi/lo into sKb slots
        #pragma unroll
        for (int nj = 0; nj < 4; nj++) {
            int c = wn0 + nj * 8 + t4 * 2;
            float v0 = p[nj][0], v1 = p[nj][1];
            float h0 = __bfloat162float(__float2bfloat16_rn(v0));
            float h1 = __bfloat162float(__float2bfloat16_rn(v1));
            *(u32*)&sPh[wm0 + g][c] = pack_bf16x2(v0, v1);
            *(u32*)&sPl[wm0 + g][c] = pack_bf16x2(v0 - h0, v1 - h1);
            v0 = p[nj][2]; v1 = p[nj][3];
            h0 = __bfloat162float(__float2bfloat16_rn(v0));
            h1 = __bfloat162float(__float2bfloat16_rn(v1));
            *(u32*)&sPh[wm0 + 8 + g][c] = pack_bf16x2(v0, v1);
            *(u32*)&sPl[wm0 + 8 + g][c] = pack_bf16x2(v0 - h0, v1 - h1);
        }
        CPW0();   // V arrived
        __syncthreads();

        // PV MMA: A = P (normalized), B = V^T
        #pragma unroll
        for (int kk = 0; kk < 64; kk += 16) {
            u32 aph[4], apl[4];
            u32 adr = smem_u32(&sPh[wm0 + lr][kk + lc * 8]);
            ldsm_x4(adr, aph[0], aph[1], aph[2], aph[3]);
            adr = smem_u32(&sPl[wm0 + lr][kk + lc * 8]);
            ldsm_x4(adr, apl[0], apl[1], apl[2], apl[3]);
            u32 bvh[2][4], bvl[2][4];
            #pragma unroll
            for (int nj2 = 0; nj2 < 2; nj2++) {
                adr = smem_u32(&sVh[kk + lr][wn0 + nj2 * 16 + lc * 8]);
                ldsm_x4t(adr, bvh[nj2][0], bvh[nj2][1], bvh[nj2][2], bvh[nj2][3]);
                adr = smem_u32(&sVl[kk + lr][wn0 + nj2 * 16 + lc * 8]);
                ldsm_x4t(adr, bvl[nj2][0], bvl[nj2][1], bvl[nj2][2], bvl[nj2][3]);
            }
            #pragma unroll
            for (int nj = 0; nj < 4; nj++) {
                int j2 = nj >> 1, hf = (nj & 1) * 2;
                mma_bf16(acc3[nj], aph, bvh[j2][hf], bvh[j2][hf + 1]);
                mma_bf16(acc3[nj], aph, bvl[j2][hf], bvl[j2][hf + 1]);
                mma_bf16(acc3[nj], apl, bvh[j2][hf], bvh[j2][hf + 1]);
            }
        }
    }

    // ctx epilogue (already normalized): write bf16 hi/lo
    #pragma unroll
    for (int nj = 0; nj < 4; nj++)
        #pragma unroll
        for (int rr = 0; rr < 2; rr++) {
            int rl = wm0 + g + rr * 8;
            float v0 = acc3[nj][rr * 2];
            float v1 = acc3[nj][rr * 2 + 1];
            float h0 = __bfloat162float(__float2bfloat16_rn(v0));
            float h1 = __bfloat162float(__float2bfloat16_rn(v1));
            size_t off = (size_t)(t0 + rl) * 768 + hh * 64 + wn0 + nj * 8 + t4 * 2;
            *(u32*)(g_ch + off) = pack_bf16x2(v0, v1);
            *(u32*)(g_cl + off) = pack_bf16x2(v0 - h0, v1 - h1);
        }
}

// ---------------- launch ----------------------------------------------------
extern "C" void kernel_launch(void* const* d_in, const int* in_sizes, int n_in,
                              void* d_out, int out_size)
{
    const float* x     = (const float*)d_in[0];
    const float* Wq    = (const float*)d_in[1];
    const float* Wk    = (const float*)d_in[2];
    const float* Wv    = (const float*)d_in[3];
    const float* Wo    = (const float*)d_in[4];
    const float* gates = (const float*)d_in[5];
    const float* u     = (const float*)d_in[6];
    float* out  = (float*)d_out;
    float* attn = out + OUT_ELEMS;

    cudaFuncSetAttribute(attn_kernel, cudaFuncAttributeMaxDynamicSharedMemorySize, ATT_SMEM);
    cudaFuncSetAttribute(bgemm_kernel, cudaFuncAttributeMaxDynamicSharedMemorySize, GEMM_SMEM);

    // split fp32 -> bf16 hi/lo (one launch)
    cvt_kernel<<<(CVT_TOTAL + 255)/256, 256>>>(x, Wq, Wk, Wv, Wo);

    // QKV projections: one launch, z = wsel
    dim3 gq(12, 32, 3);
    bgemm_kernel<<<gq, 256, GEMM_SMEM>>>(nullptr, -1);

    // d bias from K (hi+lo reconstruct)
    dbias_kernel<<<12, 1024>>>(u);

    // banded gated attention (recompute softmax, 2 CTAs/SM)
    dim3 ga(64, 12, 1);
    attn_kernel<<<ga, 256, ATT_SMEM>>>(gates, attn);

    // output projection (fp32 out)
    dim3 go(12, 32, 1);
    bgemm_kernel<<<go, 256, GEMM_SMEM>>>(out, 3);
}